// round 2
// baseline (speedup 1.0000x reference)
#include <cuda_runtime.h>
#include <cuda_bf16.h>

#define N_NODES 100000
#define N_EDGES 3200000
#define N_GRAPHS 1000
#define HID 64
#define NL 4

// ---------------- device scratch (allocation-free: __device__ globals) ----------------
__device__ float g_h[N_NODES * HID];   // node features
__device__ float g_a[N_NODES * HID];   // a = h@W1 + b1
__device__ float g_c[N_NODES * HID];   // c = h@W3 + b3 - sumw*(h@W2)
__device__ int   g_deg[N_NODES];
__device__ float g_sumw[N_NODES];
__device__ int   g_rowptr[N_NODES + 1];
__device__ int   g_cursor[N_NODES];
__device__ int   g_src[N_EDGES];
__device__ float g_ew[N_EDGES];
__device__ int   g_idx64;              // 1 if index tensors really are int64

// ---------------- dtype probe ----------------
// JAX without x64 silently downgrades int64 -> int32. Detect which layout the
// edge_index buffer actually has. If int32, reading as int64 packs two random
// values in [0,1e5): high word nonzero w.p. ~1-1e-5 per entry -> over 64
// entries detection is deterministic-in-practice AND deterministic per input.
__global__ void k_detect(const void* ei) {
    const long long* p = (const long long*)ei;
    int ok64 = 1;
    for (int i = 0; i < 64; i++) {
        long long v = p[i];
        if (v < 0 || v >= N_NODES) { ok64 = 0; break; }
    }
    g_idx64 = ok64;
}

__device__ __forceinline__ int idx_at(const void* p, long long pos) {
    return g_idx64 ? (int)((const long long*)p)[pos] : ((const int*)p)[pos];
}
__device__ __forceinline__ int clampi(int v, int hi) {
    return v < 0 ? 0 : (v >= hi ? hi - 1 : v);
}

// ---------------- CSR build ----------------
__global__ void k_zero() {
    int i = blockIdx.x * blockDim.x + threadIdx.x;
    if (i < N_NODES) { g_deg[i] = 0; g_sumw[i] = 0.f; }
}

__global__ void k_hist(const void* __restrict__ ei, const float* __restrict__ ea) {
    int e = blockIdx.x * blockDim.x + threadIdx.x;
    if (e < N_EDGES) {
        int dst = clampi(idx_at(ei, (long long)N_EDGES + e), N_NODES);
        atomicAdd(&g_deg[dst], 1);
        atomicAdd(&g_sumw[dst], ea[e]);
    }
}

// single-block scan: 1024 threads, each owns a contiguous chunk
__global__ void k_scan() {
    __shared__ int sh[1024];
    const int CH = (N_NODES + 1023) / 1024;   // 98
    int t = threadIdx.x;
    int base = t * CH;
    int s = 0;
    for (int i = 0; i < CH; i++) {
        int idx = base + i;
        if (idx < N_NODES) s += g_deg[idx];
    }
    sh[t] = s;
    __syncthreads();
    for (int off = 1; off < 1024; off <<= 1) {
        int v = (t >= off) ? sh[t - off] : 0;
        __syncthreads();
        sh[t] += v;
        __syncthreads();
    }
    int run = (t == 0) ? 0 : sh[t - 1];
    for (int i = 0; i < CH; i++) {
        int idx = base + i;
        if (idx < N_NODES) {
            g_rowptr[idx] = run;
            g_cursor[idx] = run;
            run += g_deg[idx];
        }
    }
    if (t == 0) g_rowptr[N_NODES] = N_EDGES;
}

__global__ void k_fill(const void* __restrict__ ei, const float* __restrict__ ea) {
    int e = blockIdx.x * blockDim.x + threadIdx.x;
    if (e < N_EDGES) {
        int src = clampi(idx_at(ei, e), N_NODES);
        int dst = clampi(idx_at(ei, (long long)N_EDGES + e), N_NODES);
        int pos = atomicAdd(&g_cursor[dst], 1);
        if (pos < N_EDGES) {
            g_src[pos] = src;
            g_ew[pos]  = ea[e];
        }
    }
}

// ---------------- embed: h = x @ emb_w + emb_b  (x is N x 4) ----------------
__global__ void k_embed(const float* __restrict__ x, const float* __restrict__ w,
                        const float* __restrict__ b) {
    int i = blockIdx.x * blockDim.x + threadIdx.x;
    if (i < N_NODES * HID) {
        int v = i >> 6, k = i & 63;
        const float* xr = x + v * 4;
        float acc = b[k];
#pragma unroll
        for (int j = 0; j < 4; j++) acc += xr[j] * w[j * HID + k];
        g_h[i] = acc;
    }
}

// ---------------- fused 3-matrix node GEMM (static smem <= 48KB) ----------------
// a = h@W1 + b1 ; c = h@W3 + b3 - sumw*(h@W2)
// 64 rows/block, 256 threads, 4x4 per thread per matrix. The 3 weight matrices
// stream through ONE 16KB smem buffer (3 passes over k), h tile stays resident
// transposed. Static smem = 17408 + 16384 = 33792 B.
#define HT_STRIDE 68

#define GEMM_PASS(WPTR, ACC)                                                  \
    {                                                                         \
        __syncthreads();                                                      \
        const float4* Wv = (const float4*)(WPTR);                             \
        float4* wd = (float4*)ws;                                             \
        for (int i = t; i < 1024; i += 256) wd[i] = Wv[i];                    \
        __syncthreads();                                                      \
        _Pragma("unroll 8")                                                   \
        for (int k = 0; k < 64; k++) {                                        \
            float4 h4 = *(const float4*)&hsT[k * HT_STRIDE + r0];             \
            float4 w4 = *(const float4*)&ws[k * 64 + c0];                     \
            float hr[4] = { h4.x, h4.y, h4.z, h4.w };                         \
            float wr[4] = { w4.x, w4.y, w4.z, w4.w };                         \
            _Pragma("unroll")                                                 \
            for (int i = 0; i < 4; i++)                                       \
                _Pragma("unroll")                                             \
                for (int j = 0; j < 4; j++)                                   \
                    ACC[i * 4 + j] += hr[i] * wr[j];                          \
        }                                                                     \
    }

__global__ void __launch_bounds__(256) k_gemm(
    const float* __restrict__ W1, const float* __restrict__ B1,
    const float* __restrict__ W2, const float* __restrict__ W3,
    const float* __restrict__ B3)
{
    __shared__ float hsT[64 * HT_STRIDE];
    __shared__ float ws[4096];

    const int t = threadIdx.x;
    const int row0 = blockIdx.x * 64;

    // load h tile, store transposed
    for (int i = t; i < 1024; i += 256) {
        int r = i >> 4, c4 = i & 15;
        int grow = row0 + r;
        float4 hv = make_float4(0.f, 0.f, 0.f, 0.f);
        if (grow < N_NODES) hv = ((const float4*)g_h)[grow * 16 + c4];
        int k = c4 * 4;
        hsT[(k + 0) * HT_STRIDE + r] = hv.x;
        hsT[(k + 1) * HT_STRIDE + r] = hv.y;
        hsT[(k + 2) * HT_STRIDE + r] = hv.z;
        hsT[(k + 3) * HT_STRIDE + r] = hv.w;
    }

    const int rg = t >> 4, cg = t & 15;
    const int r0 = rg * 4, c0 = cg * 4;

    float acc1[16], acc2[16], acc3[16];
#pragma unroll
    for (int i = 0; i < 16; i++) { acc1[i] = 0.f; acc2[i] = 0.f; acc3[i] = 0.f; }

    GEMM_PASS(W1, acc1)
    GEMM_PASS(W2, acc2)
    GEMM_PASS(W3, acc3)

    float4 b1v = *(const float4*)&B1[c0];
    float4 b3v = *(const float4*)&B3[c0];
#pragma unroll
    for (int i = 0; i < 4; i++) {
        int grow = row0 + r0 + i;
        if (grow < N_NODES) {
            float sw = g_sumw[grow];
            float4 av, cv;
            av.x = acc1[i * 4 + 0] + b1v.x;
            av.y = acc1[i * 4 + 1] + b1v.y;
            av.z = acc1[i * 4 + 2] + b1v.z;
            av.w = acc1[i * 4 + 3] + b1v.w;
            cv.x = acc3[i * 4 + 0] + b3v.x - sw * acc2[i * 4 + 0];
            cv.y = acc3[i * 4 + 1] + b3v.y - sw * acc2[i * 4 + 1];
            cv.z = acc3[i * 4 + 2] + b3v.z - sw * acc2[i * 4 + 2];
            cv.w = acc3[i * 4 + 3] + b3v.w - sw * acc2[i * 4 + 3];
            ((float4*)g_a)[grow * 16 + cg] = av;
            ((float4*)g_c)[grow * 16 + cg] = cv;
        }
    }
}

// ---------------- edge aggregation (CSR, no atomics): h = relu(sum ew*a[src] + c) ----------------
__global__ void __launch_bounds__(128) k_edge() {
    int v = blockIdx.x * 2 + (threadIdx.x >> 6);
    int k = threadIdx.x & 63;
    if (v >= N_NODES) return;
    int lo = g_rowptr[v], hi = g_rowptr[v + 1];
    float acc = g_c[v * HID + k];
    int e = lo;
    for (; e + 3 < hi; e += 4) {
        int   s0 = g_src[e],     s1 = g_src[e + 1], s2 = g_src[e + 2], s3 = g_src[e + 3];
        float w0 = g_ew[e],      w1 = g_ew[e + 1],  w2 = g_ew[e + 2],  w3 = g_ew[e + 3];
        float a0 = g_a[s0 * HID + k];
        float a1 = g_a[s1 * HID + k];
        float a2 = g_a[s2 * HID + k];
        float a3 = g_a[s3 * HID + k];
        acc += w0 * a0; acc += w1 * a1; acc += w2 * a2; acc += w3 * a3;
    }
    for (; e < hi; e++) acc += g_ew[e] * g_a[g_src[e] * HID + k];
    g_h[v * HID + k] = fmaxf(acc, 0.f);
}

// ---------------- pool + MLP head ----------------
__device__ __forceinline__ int lb_idx(const void* b, int val) {
    int lo = 0, hi = N_NODES;
    if (g_idx64) {
        const long long* p = (const long long*)b;
        long long v = (long long)val;
        while (lo < hi) { int m = (lo + hi) >> 1; if (p[m] < v) lo = m + 1; else hi = m; }
    } else {
        const int* p = (const int*)b;
        while (lo < hi) { int m = (lo + hi) >> 1; if (p[m] < val) lo = m + 1; else hi = m; }
    }
    return lo;
}

__global__ void __launch_bounds__(64) k_pool(
    const void* __restrict__ batch,
    const float* __restrict__ l1w, const float* __restrict__ l1b,
    const float* __restrict__ l2w, const float* __restrict__ l2b,
    float* __restrict__ out)
{
    int g = blockIdx.x;
    int k = threadIdx.x;
    __shared__ int s_lo, s_hi;
    __shared__ float gx[HID], hh[HID];
    if (k == 0) s_lo = lb_idx(batch, g);
    if (k == 1) s_hi = lb_idx(batch, g + 1);
    __syncthreads();
    int lo = s_lo, hi = s_hi;
    float s = 0.f;
    for (int v = lo; v < hi; v++) s += g_h[v * HID + k];
    float cnt = (float)(hi - lo);
    gx[k] = s / fmaxf(cnt, 1.f);
    __syncthreads();
    float acc = l1b[k];
#pragma unroll 8
    for (int i = 0; i < HID; i++) acc += gx[i] * l1w[i * HID + k];
    hh[k] = fmaxf(acc, 0.f);
    __syncthreads();
    if (k < 3) {
        float o = l2b[k];
#pragma unroll 8
        for (int i = 0; i < HID; i++) o += hh[i] * l2w[i * 3 + k];
        out[g * 3 + k] = o;
    }
}

// ---------------- launch ----------------
extern "C" void kernel_launch(void* const* d_in, const int* in_sizes, int n_in,
                              void* d_out, int out_size) {
    const float* x       = (const float*)d_in[0];
    const void*  eindex  = d_in[1];
    const float* eattr   = (const float*)d_in[2];
    const void*  batch   = d_in[3];
    const float* emb_w   = (const float*)d_in[4];
    const float* emb_b   = (const float*)d_in[5];
    const float* conv_w1 = (const float*)d_in[6];
    const float* conv_b1 = (const float*)d_in[7];
    const float* conv_w2 = (const float*)d_in[8];
    const float* conv_w3 = (const float*)d_in[9];
    const float* conv_b3 = (const float*)d_in[10];
    const float* lin1_w  = (const float*)d_in[11];
    const float* lin1_b  = (const float*)d_in[12];
    const float* lin2_w  = (const float*)d_in[13];
    const float* lin2_b  = (const float*)d_in[14];
    float*       out     = (float*)d_out;

    // dtype probe + CSR build
    k_detect<<<1, 1>>>(eindex);
    k_zero<<<(N_NODES + 255) / 256, 256>>>();
    k_hist<<<(N_EDGES + 255) / 256, 256>>>(eindex, eattr);
    k_scan<<<1, 1024>>>();
    k_fill<<<(N_EDGES + 255) / 256, 256>>>(eindex, eattr);

    // embed
    k_embed<<<(N_NODES * HID + 255) / 256, 256>>>(x, emb_w, emb_b);

    // layers
    for (int l = 0; l < NL; l++) {
        const float* W1 = conv_w1 + l * HID * HID;
        const float* B1 = conv_b1 + l * HID;
        const float* W2 = conv_w2 + l * HID * HID;
        const float* W3 = conv_w3 + l * HID * HID;
        const float* B3 = conv_b3 + l * HID;
        k_gemm<<<(N_NODES + 63) / 64, 256>>>(W1, B1, W2, W3, B3);
        k_edge<<<(N_NODES + 1) / 2, 128>>>();
    }

    // pool + head
    k_pool<<<N_GRAPHS, 64>>>(batch, lin1_w, lin1_b, lin2_w, lin2_b, out);
}

// round 3
// speedup vs baseline: 1.0327x; 1.0327x over previous
#include <cuda_runtime.h>
#include <cuda_bf16.h>

#define N_NODES 100000
#define N_EDGES 3200000
#define N_GRAPHS 1000
#define HID 64
#define NL 4

#define SCAN_NBLK ((N_NODES + 1023) / 1024)   // 98

// ---------------- device scratch ----------------
__device__ float g_h[N_NODES * HID];
__device__ float g_a[N_NODES * HID];
__device__ float g_c[N_NODES * HID];
__device__ int   g_deg[N_NODES];
__device__ float g_sumw[N_NODES];
__device__ int   g_rowptr[N_NODES + 1];
__device__ int   g_cursor[N_NODES];
__device__ int   g_src[N_EDGES];
__device__ float g_ew[N_EDGES];
__device__ int   g_idx64;
__device__ int   g_psum[SCAN_NBLK];
__device__ int   g_poff[SCAN_NBLK];

// ---------------- f32x2 packed fma helpers ----------------
__device__ __forceinline__ unsigned long long pack2(float lo, float hi) {
    unsigned long long r;
    asm("mov.b64 %0, {%1, %2};" : "=l"(r) : "f"(lo), "f"(hi));
    return r;
}
__device__ __forceinline__ unsigned long long fma2(unsigned long long a,
                                                   unsigned long long b,
                                                   unsigned long long c) {
    unsigned long long r;
    asm("fma.rn.f32x2 %0, %1, %2, %3;" : "=l"(r) : "l"(a), "l"(b), "l"(c));
    return r;
}
__device__ __forceinline__ float2 unpack2(unsigned long long v) {
    float lo, hi;
    asm("mov.b64 {%0, %1}, %2;" : "=f"(lo), "=f"(hi) : "l"(v));
    return make_float2(lo, hi);
}

// ---------------- dtype probe ----------------
__global__ void k_detect(const void* ei) {
    const long long* p = (const long long*)ei;
    int ok64 = 1;
    for (int i = 0; i < 64; i++) {
        long long v = p[i];
        if (v < 0 || v >= N_NODES) { ok64 = 0; break; }
    }
    g_idx64 = ok64;
}

__device__ __forceinline__ int idx_at(const void* p, long long pos) {
    return g_idx64 ? (int)((const long long*)p)[pos] : ((const int*)p)[pos];
}
__device__ __forceinline__ int clampi(int v, int hi) {
    return v < 0 ? 0 : (v >= hi ? hi - 1 : v);
}

// ---------------- CSR build ----------------
__global__ void k_zero() {
    int i = blockIdx.x * blockDim.x + threadIdx.x;
    if (i < N_NODES) { g_deg[i] = 0; g_sumw[i] = 0.f; }
}

__global__ void k_hist(const void* __restrict__ ei, const float* __restrict__ ea) {
    int e = blockIdx.x * blockDim.x + threadIdx.x;
    if (e < N_EDGES) {
        int dst = clampi(idx_at(ei, (long long)N_EDGES + e), N_NODES);
        atomicAdd(&g_deg[dst], 1);
        atomicAdd(&g_sumw[dst], ea[e]);
    }
}

// parallel scan, stage 1: per-block sums of g_deg
__global__ void __launch_bounds__(1024) k_scan1() {
    __shared__ int sh[32];
    int i = blockIdx.x * 1024 + threadIdx.x;
    int v = (i < N_NODES) ? g_deg[i] : 0;
    // warp reduce
    for (int o = 16; o > 0; o >>= 1) v += __shfl_down_sync(0xffffffffu, v, o);
    if ((threadIdx.x & 31) == 0) sh[threadIdx.x >> 5] = v;
    __syncthreads();
    if (threadIdx.x < 32) {
        int s = sh[threadIdx.x];
        for (int o = 16; o > 0; o >>= 1) s += __shfl_down_sync(0xffffffffu, s, o);
        if (threadIdx.x == 0) g_psum[blockIdx.x] = s;
    }
}

// stage 2: exclusive scan of SCAN_NBLK partials (single block, 128 threads)
__global__ void __launch_bounds__(128) k_scan2() {
    __shared__ int sh[128];
    int t = threadIdx.x;
    sh[t] = (t < SCAN_NBLK) ? g_psum[t] : 0;
    __syncthreads();
    for (int off = 1; off < 128; off <<= 1) {
        int v = (t >= off) ? sh[t - off] : 0;
        __syncthreads();
        sh[t] += v;
        __syncthreads();
    }
    if (t < SCAN_NBLK) g_poff[t] = (t == 0) ? 0 : sh[t - 1];
}

// stage 3: per-block inclusive scan + offset -> rowptr/cursor
__global__ void __launch_bounds__(1024) k_scan3() {
    __shared__ int sh[1024];
    int t = threadIdx.x;
    int i = blockIdx.x * 1024 + t;
    int d = (i < N_NODES) ? g_deg[i] : 0;
    sh[t] = d;
    __syncthreads();
    for (int off = 1; off < 1024; off <<= 1) {
        int v = (t >= off) ? sh[t - off] : 0;
        __syncthreads();
        sh[t] += v;
        __syncthreads();
    }
    if (i < N_NODES) {
        int excl = g_poff[blockIdx.x] + sh[t] - d;
        g_rowptr[i] = excl;
        g_cursor[i] = excl;
    }
    if (i == N_NODES - 1 || (blockIdx.x == gridDim.x - 1 && t == 1023))
        g_rowptr[N_NODES] = N_EDGES;
}

__global__ void k_fill(const void* __restrict__ ei, const float* __restrict__ ea) {
    int e = blockIdx.x * blockDim.x + threadIdx.x;
    if (e < N_EDGES) {
        int src = clampi(idx_at(ei, e), N_NODES);
        int dst = clampi(idx_at(ei, (long long)N_EDGES + e), N_NODES);
        int pos = atomicAdd(&g_cursor[dst], 1);
        if (pos < N_EDGES) {
            g_src[pos] = src;
            g_ew[pos]  = ea[e];
        }
    }
}

// ---------------- embed ----------------
__global__ void k_embed(const float* __restrict__ x, const float* __restrict__ w,
                        const float* __restrict__ b) {
    int i = blockIdx.x * blockDim.x + threadIdx.x;
    if (i < N_NODES * HID) {
        int v = i >> 6, k = i & 63;
        const float* xr = x + v * 4;
        float acc = b[k];
#pragma unroll
        for (int j = 0; j < 4; j++) acc += xr[j] * w[j * HID + k];
        g_h[i] = acc;
    }
}

// ---------------- fused 3-matrix node GEMM, f32x2 packed FFMA ----------------
// a = h@W1 + b1 ; c = h@W3 + b3 - sumw*(h@W2)
// 64 rows/block, 256 threads, 4 rows x 4 cols per thread per matrix,
// accumulators packed as 2-wide f32x2 (8 per matrix). Weights stream through
// one 16KB smem buffer (3 passes). Static smem = 17408 + 16384 = 33792 B.
#define HT_STRIDE 68

#define GEMM_PASS(WPTR, ACCP)                                                 \
    {                                                                         \
        __syncthreads();                                                      \
        const float4* Wv = (const float4*)(WPTR);                             \
        float4* wd = (float4*)ws;                                             \
        for (int i = t; i < 1024; i += 256) wd[i] = Wv[i];                    \
        __syncthreads();                                                      \
        _Pragma("unroll 8")                                                   \
        for (int k = 0; k < 64; k++) {                                        \
            float4 h4 = *(const float4*)&hsT[k * HT_STRIDE + r0];             \
            ulonglong2 w2 = *(const ulonglong2*)&ws[k * 64 + c0];             \
            unsigned long long hp0 = pack2(h4.x, h4.x);                       \
            unsigned long long hp1 = pack2(h4.y, h4.y);                       \
            unsigned long long hp2 = pack2(h4.z, h4.z);                       \
            unsigned long long hp3 = pack2(h4.w, h4.w);                       \
            ACCP[0] = fma2(hp0, w2.x, ACCP[0]);                               \
            ACCP[1] = fma2(hp0, w2.y, ACCP[1]);                               \
            ACCP[2] = fma2(hp1, w2.x, ACCP[2]);                               \
            ACCP[3] = fma2(hp1, w2.y, ACCP[3]);                               \
            ACCP[4] = fma2(hp2, w2.x, ACCP[4]);                               \
            ACCP[5] = fma2(hp2, w2.y, ACCP[5]);                               \
            ACCP[6] = fma2(hp3, w2.x, ACCP[6]);                               \
            ACCP[7] = fma2(hp3, w2.y, ACCP[7]);                               \
        }                                                                     \
    }

__global__ void __launch_bounds__(256) k_gemm(
    const float* __restrict__ W1, const float* __restrict__ B1,
    const float* __restrict__ W2, const float* __restrict__ W3,
    const float* __restrict__ B3)
{
    __shared__ float hsT[64 * HT_STRIDE];
    __shared__ float ws[4096];

    const int t = threadIdx.x;
    const int row0 = blockIdx.x * 64;

    // load h tile, store transposed
    for (int i = t; i < 1024; i += 256) {
        int r = i >> 4, c4 = i & 15;
        int grow = row0 + r;
        float4 hv = make_float4(0.f, 0.f, 0.f, 0.f);
        if (grow < N_NODES) hv = ((const float4*)g_h)[grow * 16 + c4];
        int k = c4 * 4;
        hsT[(k + 0) * HT_STRIDE + r] = hv.x;
        hsT[(k + 1) * HT_STRIDE + r] = hv.y;
        hsT[(k + 2) * HT_STRIDE + r] = hv.z;
        hsT[(k + 3) * HT_STRIDE + r] = hv.w;
    }

    const int rg = t >> 4, cg = t & 15;
    const int r0 = rg * 4, c0 = cg * 4;

    unsigned long long p1[8], p2[8], p3[8];
#pragma unroll
    for (int i = 0; i < 8; i++) { p1[i] = 0ull; p2[i] = 0ull; p3[i] = 0ull; }

    GEMM_PASS(W1, p1)
    GEMM_PASS(W2, p2)
    GEMM_PASS(W3, p3)

    float4 b1v = *(const float4*)&B1[c0];
    float4 b3v = *(const float4*)&B3[c0];
#pragma unroll
    for (int i = 0; i < 4; i++) {
        int grow = row0 + r0 + i;
        if (grow < N_NODES) {
            float sw = g_sumw[grow];
            float2 a01 = unpack2(p1[i * 2 + 0]);
            float2 a23 = unpack2(p1[i * 2 + 1]);
            float2 q01 = unpack2(p2[i * 2 + 0]);
            float2 q23 = unpack2(p2[i * 2 + 1]);
            float2 c01 = unpack2(p3[i * 2 + 0]);
            float2 c23 = unpack2(p3[i * 2 + 1]);
            float4 av, cv;
            av.x = a01.x + b1v.x;  av.y = a01.y + b1v.y;
            av.z = a23.x + b1v.z;  av.w = a23.y + b1v.w;
            cv.x = c01.x + b3v.x - sw * q01.x;
            cv.y = c01.y + b3v.y - sw * q01.y;
            cv.z = c23.x + b3v.z - sw * q23.x;
            cv.w = c23.y + b3v.w - sw * q23.y;
            ((float4*)g_a)[grow * 16 + cg] = av;
            ((float4*)g_c)[grow * 16 + cg] = cv;
        }
    }
}

// ---------------- edge aggregation (CSR, float2 lanes, no atomics) ----------------
// h = relu(sum_e ew * a[src] + c). 32 threads per node (float2 per thread),
// 4 nodes per 128-thread block.
__global__ void __launch_bounds__(128) k_edge() {
    int v = blockIdx.x * 4 + (threadIdx.x >> 5);
    int kp = threadIdx.x & 31;
    if (v >= N_NODES) return;
    int lo = g_rowptr[v], hi = g_rowptr[v + 1];
    const float2* A = (const float2*)g_a;
    float2 acc = ((const float2*)g_c)[v * 32 + kp];
    int e = lo;
    for (; e + 7 < hi; e += 8) {
        int   s[8];
        float w[8];
#pragma unroll
        for (int j = 0; j < 8; j++) { s[j] = g_src[e + j]; w[j] = g_ew[e + j]; }
#pragma unroll
        for (int j = 0; j < 8; j++) {
            float2 av = A[s[j] * 32 + kp];
            acc.x += w[j] * av.x;
            acc.y += w[j] * av.y;
        }
    }
    for (; e < hi; e++) {
        float2 av = A[g_src[e] * 32 + kp];
        float  w  = g_ew[e];
        acc.x += w * av.x;
        acc.y += w * av.y;
    }
    acc.x = fmaxf(acc.x, 0.f);
    acc.y = fmaxf(acc.y, 0.f);
    ((float2*)g_h)[v * 32 + kp] = acc;
}

// ---------------- pool + MLP head ----------------
__device__ __forceinline__ int lb_idx(const void* b, int val) {
    int lo = 0, hi = N_NODES;
    if (g_idx64) {
        const long long* p = (const long long*)b;
        long long v = (long long)val;
        while (lo < hi) { int m = (lo + hi) >> 1; if (p[m] < v) lo = m + 1; else hi = m; }
    } else {
        const int* p = (const int*)b;
        while (lo < hi) { int m = (lo + hi) >> 1; if (p[m] < val) lo = m + 1; else hi = m; }
    }
    return lo;
}

__global__ void __launch_bounds__(64) k_pool(
    const void* __restrict__ batch,
    const float* __restrict__ l1w, const float* __restrict__ l1b,
    const float* __restrict__ l2w, const float* __restrict__ l2b,
    float* __restrict__ out)
{
    int g = blockIdx.x;
    int k = threadIdx.x;
    __shared__ int s_lo, s_hi;
    __shared__ float gx[HID], hh[HID];
    if (k == 0) s_lo = lb_idx(batch, g);
    if (k == 1) s_hi = lb_idx(batch, g + 1);
    __syncthreads();
    int lo = s_lo, hi = s_hi;
    float s = 0.f;
    for (int v = lo; v < hi; v++) s += g_h[v * HID + k];
    float cnt = (float)(hi - lo);
    gx[k] = s / fmaxf(cnt, 1.f);
    __syncthreads();
    float acc = l1b[k];
#pragma unroll 8
    for (int i = 0; i < HID; i++) acc += gx[i] * l1w[i * HID + k];
    hh[k] = fmaxf(acc, 0.f);
    __syncthreads();
    if (k < 3) {
        float o = l2b[k];
#pragma unroll 8
        for (int i = 0; i < HID; i++) o += hh[i] * l2w[i * 3 + k];
        out[g * 3 + k] = o;
    }
}

// ---------------- launch ----------------
extern "C" void kernel_launch(void* const* d_in, const int* in_sizes, int n_in,
                              void* d_out, int out_size) {
    const float* x       = (const float*)d_in[0];
    const void*  eindex  = d_in[1];
    const float* eattr   = (const float*)d_in[2];
    const void*  batch   = d_in[3];
    const float* emb_w   = (const float*)d_in[4];
    const float* emb_b   = (const float*)d_in[5];
    const float* conv_w1 = (const float*)d_in[6];
    const float* conv_b1 = (const float*)d_in[7];
    const float* conv_w2 = (const float*)d_in[8];
    const float* conv_w3 = (const float*)d_in[9];
    const float* conv_b3 = (const float*)d_in[10];
    const float* lin1_w  = (const float*)d_in[11];
    const float* lin1_b  = (const float*)d_in[12];
    const float* lin2_w  = (const float*)d_in[13];
    const float* lin2_b  = (const float*)d_in[14];
    float*       out     = (float*)d_out;

    k_detect<<<1, 1>>>(eindex);
    k_zero<<<(N_NODES + 255) / 256, 256>>>();
    k_hist<<<(N_EDGES + 255) / 256, 256>>>(eindex, eattr);
    k_scan1<<<SCAN_NBLK, 1024>>>();
    k_scan2<<<1, 128>>>();
    k_scan3<<<SCAN_NBLK, 1024>>>();
    k_fill<<<(N_EDGES + 255) / 256, 256>>>(eindex, eattr);

    k_embed<<<(N_NODES * HID + 255) / 256, 256>>>(x, emb_w, emb_b);

    for (int l = 0; l < NL; l++) {
        const float* W1 = conv_w1 + l * HID * HID;
        const float* B1 = conv_b1 + l * HID;
        const float* W2 = conv_w2 + l * HID * HID;
        const float* W3 = conv_w3 + l * HID * HID;
        const float* B3 = conv_b3 + l * HID;
        k_gemm<<<(N_NODES + 63) / 64, 256>>>(W1, B1, W2, W3, B3);
        k_edge<<<(N_NODES + 3) / 4, 128>>>();
    }

    k_pool<<<N_GRAPHS, 64>>>(batch, lin1_w, lin1_b, lin2_w, lin2_b, out);
}

// round 5
// speedup vs baseline: 1.2096x; 1.1713x over previous
#include <cuda_runtime.h>
#include <cuda_bf16.h>

#define N_NODES 100000
#define N_EDGES 3200000
#define N_GRAPHS 1000
#define HID 64
#define NL 4

#define SCAN_NBLK ((N_NODES + 1023) / 1024)   // 98

// ---------------- device scratch ----------------
__device__ float g_h[N_NODES * HID];
__device__ float g_a[N_NODES * HID];
__device__ float g_c[N_NODES * HID];
__device__ int   g_deg[N_NODES];
__device__ float g_sumw[N_NODES];
__device__ int   g_rowptr[N_NODES + 1];
__device__ int   g_cursor[N_NODES];
__device__ int   g_src[N_EDGES];
__device__ float g_ew[N_EDGES];
__device__ int   g_idx64;
__device__ int   g_psum[SCAN_NBLK];

__device__ __forceinline__ int idx_at(const void* p, long long pos) {
    return g_idx64 ? (int)((const long long*)p)[pos] : ((const int*)p)[pos];
}
__device__ __forceinline__ int clampi(int v, int hi) {
    return v < 0 ? 0 : (v >= hi ? hi - 1 : v);
}

// ---------------- fused init: dtype probe + zero + embed ----------------
// embed: h = x @ emb_w + emb_b (x is N x 4). Also zeros deg/sumw, and block 0
// thread 0 probes whether index tensors are really int64 (JAX w/o x64 ships
// int32 under an int64 label; reading int32 pairs as int64 yields values
// outside [0, N_NODES) with overwhelming probability over 64 entries).
__global__ void k_init(const void* __restrict__ ei,
                       const float* __restrict__ x,
                       const float* __restrict__ w,
                       const float* __restrict__ b) {
    int i = blockIdx.x * blockDim.x + threadIdx.x;
    if (i == 0) {
        const long long* p = (const long long*)ei;
        int ok64 = 1;
        for (int j = 0; j < 64; j++) {
            long long v = p[j];
            if (v < 0 || v >= N_NODES) { ok64 = 0; break; }
        }
        g_idx64 = ok64;
    }
    if (i < N_NODES) { g_deg[i] = 0; g_sumw[i] = 0.f; }
    if (i < N_NODES * HID) {
        int v = i >> 6, k = i & 63;
        const float* xr = x + v * 4;
        float acc = b[k];
#pragma unroll
        for (int j = 0; j < 4; j++) acc += xr[j] * w[j * HID + k];
        g_h[i] = acc;
    }
}

// ---------------- CSR build ----------------
__global__ void k_hist(const void* __restrict__ ei, const float* __restrict__ ea) {
    int e = blockIdx.x * blockDim.x + threadIdx.x;
    if (e < N_EDGES) {
        int dst = clampi(idx_at(ei, (long long)N_EDGES + e), N_NODES);
        atomicAdd(&g_deg[dst], 1);
        atomicAdd(&g_sumw[dst], ea[e]);
    }
}

// scan stage 1: per-block sums of g_deg
__global__ void __launch_bounds__(1024) k_scan1() {
    __shared__ int sh[32];
    int i = blockIdx.x * 1024 + threadIdx.x;
    int v = (i < N_NODES) ? g_deg[i] : 0;
    for (int o = 16; o > 0; o >>= 1) v += __shfl_down_sync(0xffffffffu, v, o);
    if ((threadIdx.x & 31) == 0) sh[threadIdx.x >> 5] = v;
    __syncthreads();
    if (threadIdx.x < 32) {
        int s = sh[threadIdx.x];
        for (int o = 16; o > 0; o >>= 1) s += __shfl_down_sync(0xffffffffu, s, o);
        if (threadIdx.x == 0) g_psum[blockIdx.x] = s;
    }
}

// scan stage 2 (fused): each block sums psum[0..blk) itself, then local
// inclusive scan + offset -> rowptr/cursor. 98 partials -> cheap redundancy.
__global__ void __launch_bounds__(1024) k_scan3() {
    __shared__ int sh[1024];
    __shared__ int swr[32];
    __shared__ int soff;
    int t = threadIdx.x;

    // block offset = sum of psums of preceding blocks
    int po = (t < blockIdx.x) ? g_psum[t] : 0;   // SCAN_NBLK (98) < 1024
    for (int o = 16; o > 0; o >>= 1) po += __shfl_down_sync(0xffffffffu, po, o);
    if ((t & 31) == 0) swr[t >> 5] = po;
    __syncthreads();
    if (t < 32) {
        int s = swr[t];
        for (int o = 16; o > 0; o >>= 1) s += __shfl_down_sync(0xffffffffu, s, o);
        if (t == 0) soff = s;
    }

    int i = blockIdx.x * 1024 + t;
    int d = (i < N_NODES) ? g_deg[i] : 0;
    sh[t] = d;
    __syncthreads();
    for (int off = 1; off < 1024; off <<= 1) {
        int v = (t >= off) ? sh[t - off] : 0;
        __syncthreads();
        sh[t] += v;
        __syncthreads();
    }
    if (i < N_NODES) {
        int excl = soff + sh[t] - d;
        g_rowptr[i] = excl;
        g_cursor[i] = excl;
    }
    if (i == 0) g_rowptr[N_NODES] = N_EDGES;
}

__global__ void k_fill(const void* __restrict__ ei, const float* __restrict__ ea) {
    int e = blockIdx.x * blockDim.x + threadIdx.x;
    if (e < N_EDGES) {
        int src = clampi(idx_at(ei, e), N_NODES);
        int dst = clampi(idx_at(ei, (long long)N_EDGES + e), N_NODES);
        int pos = atomicAdd(&g_cursor[dst], 1);
        if (pos < N_EDGES) {
            g_src[pos] = src;
            g_ew[pos]  = ea[e];
        }
    }
}

// ---------------- fused 3-matrix node GEMM (scalar FFMA, proven form) ----------------
// a = h@W1 + b1 ; c = h@W3 + b3 - sumw*(h@W2)
// 64 rows/block, 256 threads, 4x4 per thread per matrix. Weights stream
// through one 16KB smem buffer (3 passes); transposed h tile resident.
#define HT_STRIDE 68

#define GEMM_PASS(WPTR, ACC)                                                  \
    {                                                                         \
        __syncthreads();                                                      \
        const float4* Wv = (const float4*)(WPTR);                             \
        float4* wd = (float4*)ws;                                             \
        for (int i = t; i < 1024; i += 256) wd[i] = Wv[i];                    \
        __syncthreads();                                                      \
        _Pragma("unroll 8")                                                   \
        for (int k = 0; k < 64; k++) {                                        \
            float4 h4 = *(const float4*)&hsT[k * HT_STRIDE + r0];             \
            float4 w4 = *(const float4*)&ws[k * 64 + c0];                     \
            float hr[4] = { h4.x, h4.y, h4.z, h4.w };                         \
            float wr[4] = { w4.x, w4.y, w4.z, w4.w };                         \
            _Pragma("unroll")                                                 \
            for (int i = 0; i < 4; i++)                                       \
                _Pragma("unroll")                                             \
                for (int j = 0; j < 4; j++)                                   \
                    ACC[i * 4 + j] += hr[i] * wr[j];                          \
        }                                                                     \
    }

__global__ void __launch_bounds__(256) k_gemm(
    const float* __restrict__ W1, const float* __restrict__ B1,
    const float* __restrict__ W2, const float* __restrict__ W3,
    const float* __restrict__ B3)
{
    __shared__ float hsT[64 * HT_STRIDE];
    __shared__ float ws[4096];

    const int t = threadIdx.x;
    const int row0 = blockIdx.x * 64;

    for (int i = t; i < 1024; i += 256) {
        int r = i >> 4, c4 = i & 15;
        int grow = row0 + r;
        float4 hv = make_float4(0.f, 0.f, 0.f, 0.f);
        if (grow < N_NODES) hv = ((const float4*)g_h)[grow * 16 + c4];
        int k = c4 * 4;
        hsT[(k + 0) * HT_STRIDE + r] = hv.x;
        hsT[(k + 1) * HT_STRIDE + r] = hv.y;
        hsT[(k + 2) * HT_STRIDE + r] = hv.z;
        hsT[(k + 3) * HT_STRIDE + r] = hv.w;
    }

    const int rg = t >> 4, cg = t & 15;
    const int r0 = rg * 4, c0 = cg * 4;

    float acc1[16], acc2[16], acc3[16];
#pragma unroll
    for (int i = 0; i < 16; i++) { acc1[i] = 0.f; acc2[i] = 0.f; acc3[i] = 0.f; }

    GEMM_PASS(W1, acc1)
    GEMM_PASS(W2, acc2)
    GEMM_PASS(W3, acc3)

    float4 b1v = *(const float4*)&B1[c0];
    float4 b3v = *(const float4*)&B3[c0];
#pragma unroll
    for (int i = 0; i < 4; i++) {
        int grow = row0 + r0 + i;
        if (grow < N_NODES) {
            float sw = g_sumw[grow];
            float4 av, cv;
            av.x = acc1[i * 4 + 0] + b1v.x;
            av.y = acc1[i * 4 + 1] + b1v.y;
            av.z = acc1[i * 4 + 2] + b1v.z;
            av.w = acc1[i * 4 + 3] + b1v.w;
            cv.x = acc3[i * 4 + 0] + b3v.x - sw * acc2[i * 4 + 0];
            cv.y = acc3[i * 4 + 1] + b3v.y - sw * acc2[i * 4 + 1];
            cv.z = acc3[i * 4 + 2] + b3v.z - sw * acc2[i * 4 + 2];
            cv.w = acc3[i * 4 + 3] + b3v.w - sw * acc2[i * 4 + 3];
            ((float4*)g_a)[grow * 16 + cg] = av;
            ((float4*)g_c)[grow * 16 + cg] = cv;
        }
    }
}

// ---------------- edge aggregation (CSR, 64 threads/node, unroll 8) ----------------
// h = relu(sum_e ew * a[src] + c)
__global__ void __launch_bounds__(256) k_edge() {
    int v = blockIdx.x * 4 + (threadIdx.x >> 6);
    int k = threadIdx.x & 63;
    if (v >= N_NODES) return;
    int lo = g_rowptr[v], hi = g_rowptr[v + 1];
    const float* __restrict__ A = g_a;
    float acc = g_c[v * HID + k];
    int e = lo;
    for (; e + 7 < hi; e += 8) {
        int   s[8];
        float w[8];
#pragma unroll
        for (int j = 0; j < 8; j++) { s[j] = g_src[e + j]; w[j] = g_ew[e + j]; }
        float av[8];
#pragma unroll
        for (int j = 0; j < 8; j++) av[j] = A[s[j] * HID + k];
#pragma unroll
        for (int j = 0; j < 8; j++) acc += w[j] * av[j];
    }
    for (; e < hi; e++) acc += g_ew[e] * A[g_src[e] * HID + k];
    g_h[v * HID + k] = fmaxf(acc, 0.f);
}

// ---------------- pool + MLP head ----------------
__device__ __forceinline__ int lb_idx(const void* b, int val) {
    int lo = 0, hi = N_NODES;
    if (g_idx64) {
        const long long* p = (const long long*)b;
        long long v = (long long)val;
        while (lo < hi) { int m = (lo + hi) >> 1; if (p[m] < v) lo = m + 1; else hi = m; }
    } else {
        const int* p = (const int*)b;
        while (lo < hi) { int m = (lo + hi) >> 1; if (p[m] < val) lo = m + 1; else hi = m; }
    }
    return lo;
}

__global__ void __launch_bounds__(64) k_pool(
    const void* __restrict__ batch,
    const float* __restrict__ l1w, const float* __restrict__ l1b,
    const float* __restrict__ l2w, const float* __restrict__ l2b,
    float* __restrict__ out)
{
    int g = blockIdx.x;
    int k = threadIdx.x;
    __shared__ int s_lo, s_hi;
    __shared__ float gx[HID], hh[HID];
    if (k == 0) s_lo = lb_idx(batch, g);
    if (k == 1) s_hi = lb_idx(batch, g + 1);
    __syncthreads();
    int lo = s_lo, hi = s_hi;
    float s = 0.f;
    for (int v = lo; v < hi; v++) s += g_h[v * HID + k];
    float cnt = (float)(hi - lo);
    gx[k] = s / fmaxf(cnt, 1.f);
    __syncthreads();
    float acc = l1b[k];
#pragma unroll 8
    for (int i = 0; i < HID; i++) acc += gx[i] * l1w[i * HID + k];
    hh[k] = fmaxf(acc, 0.f);
    __syncthreads();
    if (k < 3) {
        float o = l2b[k];
#pragma unroll 8
        for (int i = 0; i < HID; i++) o += hh[i] * l2w[i * 3 + k];
        out[g * 3 + k] = o;
    }
}

// ---------------- launch ----------------
// Launch order puts k_gemm at launch #6 so ncu (-s 5 -c 1) profiles it.
extern "C" void kernel_launch(void* const* d_in, const int* in_sizes, int n_in,
                              void* d_out, int out_size) {
    const float* x       = (const float*)d_in[0];
    const void*  eindex  = d_in[1];
    const float* eattr   = (const float*)d_in[2];
    const void*  batch   = d_in[3];
    const float* emb_w   = (const float*)d_in[4];
    const float* emb_b   = (const float*)d_in[5];
    const float* conv_w1 = (const float*)d_in[6];
    const float* conv_b1 = (const float*)d_in[7];
    const float* conv_w2 = (const float*)d_in[8];
    const float* conv_w3 = (const float*)d_in[9];
    const float* conv_b3 = (const float*)d_in[10];
    const float* lin1_w  = (const float*)d_in[11];
    const float* lin1_b  = (const float*)d_in[12];
    const float* lin2_w  = (const float*)d_in[13];
    const float* lin2_b  = (const float*)d_in[14];
    float*       out     = (float*)d_out;

    k_init<<<(N_NODES * HID + 255) / 256, 256>>>(eindex, x, emb_w, emb_b);   // 1
    k_hist<<<(N_EDGES + 255) / 256, 256>>>(eindex, eattr);                   // 2
    k_scan1<<<SCAN_NBLK, 1024>>>();                                          // 3
    k_scan3<<<SCAN_NBLK, 1024>>>();                                          // 4
    k_fill<<<(N_EDGES + 255) / 256, 256>>>(eindex, eattr);                   // 5

    for (int l = 0; l < NL; l++) {
        const float* W1 = conv_w1 + l * HID * HID;
        const float* B1 = conv_b1 + l * HID;
        const float* W2 = conv_w2 + l * HID * HID;
        const float* W3 = conv_w3 + l * HID * HID;
        const float* B3 = conv_b3 + l * HID;
        k_gemm<<<(N_NODES + 63) / 64, 256>>>(W1, B1, W2, W3, B3);            // 6 (l=0)
        k_edge<<<(N_NODES + 3) / 4, 256>>>();                                // 7 (l=0)
    }

    k_pool<<<N_GRAPHS, 64>>>(batch, lin1_w, lin1_b, lin2_w, lin2_b, out);
}

// round 7
// speedup vs baseline: 1.3427x; 1.1100x over previous
#include <cuda_runtime.h>
#include <cuda_bf16.h>
#include <mma.h>
#include <cstdint>

using namespace nvcuda;

#define N_NODES 100000
#define N_EDGES 3200000
#define N_GRAPHS 1000
#define HID 64
#define NL 4

#define SCAN_NBLK ((N_NODES + 1023) / 1024)   // 98
#define AST 72                                 // bf16 smem stride (elems)
#define DST 72                                 // fp32 strip stride (elems)

// ---------------- device scratch ----------------
__device__ float g_h[N_NODES * HID];
__device__ float g_a[N_NODES * HID];
__device__ float g_c[N_NODES * HID];
__device__ int   g_deg[N_NODES];
__device__ float g_sumw[N_NODES];
__device__ int   g_rowptr[N_NODES + 1];
__device__ int   g_cursor[N_NODES];
__device__ int   g_src[N_EDGES];
__device__ float g_ew[N_EDGES];
__device__ int   g_idx64;
__device__ int   g_psum[SCAN_NBLK];

__device__ __forceinline__ int idx_at(const void* p, long long pos) {
    return g_idx64 ? (int)((const long long*)p)[pos] : ((const int*)p)[pos];
}
__device__ __forceinline__ int clampi(int v, int hi) {
    return v < 0 ? 0 : (v >= hi ? hi - 1 : v);
}

// ---------------- fused init: dtype probe + zero + embed ----------------
__global__ void k_init(const void* __restrict__ ei,
                       const float* __restrict__ x,
                       const float* __restrict__ w,
                       const float* __restrict__ b) {
    int i = blockIdx.x * blockDim.x + threadIdx.x;
    if (i == 0) {
        const long long* p = (const long long*)ei;
        int ok64 = 1;
        for (int j = 0; j < 64; j++) {
            long long v = p[j];
            if (v < 0 || v >= N_NODES) { ok64 = 0; break; }
        }
        g_idx64 = ok64;
    }
    if (i < N_NODES) { g_deg[i] = 0; g_sumw[i] = 0.f; }
    if (i < N_NODES * HID) {
        int v = i >> 6, k = i & 63;
        const float* xr = x + v * 4;
        float acc = b[k];
#pragma unroll
        for (int j = 0; j < 4; j++) acc += xr[j] * w[j * HID + k];
        g_h[i] = acc;
    }
}

// ---------------- CSR build ----------------
__global__ void k_hist(const void* __restrict__ ei, const float* __restrict__ ea) {
    int e = blockIdx.x * blockDim.x + threadIdx.x;
    if (e < N_EDGES) {
        int dst = clampi(idx_at(ei, (long long)N_EDGES + e), N_NODES);
        atomicAdd(&g_deg[dst], 1);
        atomicAdd(&g_sumw[dst], ea[e]);
    }
}

__global__ void __launch_bounds__(1024) k_scan1() {
    __shared__ int sh[32];
    int i = blockIdx.x * 1024 + threadIdx.x;
    int v = (i < N_NODES) ? g_deg[i] : 0;
    for (int o = 16; o > 0; o >>= 1) v += __shfl_down_sync(0xffffffffu, v, o);
    if ((threadIdx.x & 31) == 0) sh[threadIdx.x >> 5] = v;
    __syncthreads();
    if (threadIdx.x < 32) {
        int s = sh[threadIdx.x];
        for (int o = 16; o > 0; o >>= 1) s += __shfl_down_sync(0xffffffffu, s, o);
        if (threadIdx.x == 0) g_psum[blockIdx.x] = s;
    }
}

__global__ void __launch_bounds__(1024) k_scan3() {
    __shared__ int sh[1024];
    __shared__ int swr[32];
    __shared__ int soff;
    int t = threadIdx.x;
    int po = (t < blockIdx.x) ? g_psum[t] : 0;
    for (int o = 16; o > 0; o >>= 1) po += __shfl_down_sync(0xffffffffu, po, o);
    if ((t & 31) == 0) swr[t >> 5] = po;
    __syncthreads();
    if (t < 32) {
        int s = swr[t];
        for (int o = 16; o > 0; o >>= 1) s += __shfl_down_sync(0xffffffffu, s, o);
        if (t == 0) soff = s;
    }
    int i = blockIdx.x * 1024 + t;
    int d = (i < N_NODES) ? g_deg[i] : 0;
    sh[t] = d;
    __syncthreads();
    for (int off = 1; off < 1024; off <<= 1) {
        int v = (t >= off) ? sh[t - off] : 0;
        __syncthreads();
        sh[t] += v;
        __syncthreads();
    }
    if (i < N_NODES) {
        int excl = soff + sh[t] - d;
        g_rowptr[i] = excl;
        g_cursor[i] = excl;
    }
    if (i == 0) g_rowptr[N_NODES] = N_EDGES;
}

__global__ void k_fill(const void* __restrict__ ei, const float* __restrict__ ea) {
    int e = blockIdx.x * blockDim.x + threadIdx.x;
    if (e < N_EDGES) {
        int src = clampi(idx_at(ei, e), N_NODES);
        int dst = clampi(idx_at(ei, (long long)N_EDGES + e), N_NODES);
        int pos = atomicAdd(&g_cursor[dst], 1);
        if (pos < N_EDGES) {
            g_src[pos] = src;
            g_ew[pos]  = ea[e];
        }
    }
}

// ---------------- WMMA bf16 split-precision fused 3-matrix GEMM ----------------
// D1 = h@W1 -> g_a (raw). D2 = h@W2, D3 = h@W3.
// g_c = D3 + b3 + sumw*b1 - sumw*D2   (b1 folded via sum_e ew*b1 = sumw*b1)
// Split: X = X_hi + X_lo (bf16 each); D ≈ hi*hi + lo*hi + hi*lo, fp32 accum.
// 64 rows/CTA, 4 warps, warp w owns rows w*16..w*16+15.
__global__ void __launch_bounds__(128) k_gemm_mma(
    const float* __restrict__ W1, const float* __restrict__ B1,
    const float* __restrict__ W2, const float* __restrict__ W3,
    const float* __restrict__ B3)
{
    __shared__ __align__(16) char sm[36864];
    __nv_bfloat16* sAhi = (__nv_bfloat16*)(sm);
    __nv_bfloat16* sAlo = (__nv_bfloat16*)(sm + 9216);
    __nv_bfloat16* sWhi = (__nv_bfloat16*)(sm + 18432);
    __nv_bfloat16* sWlo = (__nv_bfloat16*)(sm + 27648);
    float* stripA = (float*)sm;             // 4 warps x 16x72 fp32 (reuses A region)
    float* stripW = (float*)(sm + 18432);   // 4 warps x 16x72 fp32 (reuses W region)

    const int t = threadIdx.x;
    const int w = t >> 5;
    const int lid = t & 31;
    const int row0 = blockIdx.x * 64;
    const bool full = (row0 + 64 <= N_NODES);

    // ---- A tile: load h, split hi/lo bf16 ----
    for (int i = t; i < 2048; i += 128) {        // 64 rows x 32 float2
        int r = i >> 5, kp = i & 31;
        int grow = row0 + r;
        float2 hv = make_float2(0.f, 0.f);
        if (grow < N_NODES) hv = ((const float2*)g_h)[grow * 32 + kp];
        __nv_bfloat16 h0 = __float2bfloat16(hv.x);
        __nv_bfloat16 h1 = __float2bfloat16(hv.y);
        sAhi[r * AST + kp * 2]     = h0;
        sAhi[r * AST + kp * 2 + 1] = h1;
        sAlo[r * AST + kp * 2]     = __float2bfloat16(hv.x - __bfloat162float(h0));
        sAlo[r * AST + kp * 2 + 1] = __float2bfloat16(hv.y - __bfloat162float(h1));
    }
    __syncthreads();

    wmma::fragment<wmma::matrix_a, 16, 16, 16, __nv_bfloat16, wmma::row_major> ahi[4], alo[4];
#pragma unroll
    for (int k = 0; k < 4; k++) {
        wmma::load_matrix_sync(ahi[k], sAhi + (w * 16) * AST + k * 16, AST);
        wmma::load_matrix_sync(alo[k], sAlo + (w * 16) * AST + k * 16, AST);
    }

    const float* Ws[3] = { W1, W2, W3 };
    wmma::fragment<wmma::accumulator, 16, 16, 16, float> d3f[4];

#pragma unroll
    for (int mat = 0; mat < 3; mat++) {
        __syncthreads();   // all warps done with previous W reads / frag loads chip-wide
        const float* W = Ws[mat];
        for (int i = t; i < 2048; i += 128) {    // 64 k-rows x 32 float2
            int r = i >> 5, np = i & 31;
            float2 wv = ((const float2*)W)[r * 32 + np];
            __nv_bfloat16 h0 = __float2bfloat16(wv.x);
            __nv_bfloat16 h1 = __float2bfloat16(wv.y);
            sWhi[r * AST + np * 2]     = h0;
            sWhi[r * AST + np * 2 + 1] = h1;
            sWlo[r * AST + np * 2]     = __float2bfloat16(wv.x - __bfloat162float(h0));
            sWlo[r * AST + np * 2 + 1] = __float2bfloat16(wv.y - __bfloat162float(h1));
        }
        __syncthreads();

#pragma unroll
        for (int n = 0; n < 4; n++) {
            wmma::fragment<wmma::accumulator, 16, 16, 16, float> d;
            wmma::fill_fragment(d, 0.f);
#pragma unroll
            for (int k = 0; k < 4; k++) {
                wmma::fragment<wmma::matrix_b, 16, 16, 16, __nv_bfloat16, wmma::row_major> bh, bl;
                wmma::load_matrix_sync(bh, sWhi + (k * 16) * AST + n * 16, AST);
                wmma::mma_sync(d, ahi[k], bh, d);
                wmma::mma_sync(d, alo[k], bh, d);
                wmma::load_matrix_sync(bl, sWlo + (k * 16) * AST + n * 16, AST);
                wmma::mma_sync(d, ahi[k], bl, d);
            }
            if (mat == 0) {
                if (full) {
                    wmma::store_matrix_sync(g_a + (size_t)(row0 + w * 16) * 64 + n * 16,
                                            d, 64, wmma::mem_row_major);
                } else {
                    // guarded path via warp-private strip (A region; frags already loaded)
                    wmma::store_matrix_sync(stripA + w * 16 * DST + n * 16, d, DST,
                                            wmma::mem_row_major);
                }
            } else if (mat == 1) {
                wmma::store_matrix_sync(stripA + w * 16 * DST + n * 16, d, DST,
                                        wmma::mem_row_major);
            } else {
                d3f[n] = d;
            }
        }

        if (mat == 0 && !full) {
            __syncwarp();
            for (int i = lid; i < 256; i += 32) {   // 16 rows x 16 float4
                int r = i >> 4, q = i & 15;
                int row = row0 + w * 16 + r;
                if (row < N_NODES) {
                    const float* s = stripA + w * 16 * DST + r * DST + q * 4;
                    float4 v = make_float4(s[0], s[1], s[2], s[3]);
                    ((float4*)(g_a + (size_t)row * 64))[q] = v;
                }
            }
            __syncwarp();
        }
    }

    // ---- D3 to strips (W region) after everyone is done reading weights ----
    __syncthreads();
#pragma unroll
    for (int n = 0; n < 4; n++)
        wmma::store_matrix_sync(stripW + w * 16 * DST + n * 16, d3f[n], DST,
                                wmma::mem_row_major);
    __syncwarp();

    // ---- combine: g_c = D3 + b3 + sumw*b1 - sumw*D2 ----
    for (int i = lid; i < 256; i += 32) {           // 16 rows x 16 float4
        int r = i >> 4, q = i & 15;
        int row = row0 + w * 16 + r;
        if (row < N_NODES) {
            float sw = g_sumw[row];
            const float* s2 = stripA + w * 16 * DST + r * DST + q * 4;
            const float* s3 = stripW + w * 16 * DST + r * DST + q * 4;
            float4 b1v = ((const float4*)B1)[q];
            float4 b3v = ((const float4*)B3)[q];
            float4 cv;
            cv.x = s3[0] + b3v.x + sw * (b1v.x - s2[0]);
            cv.y = s3[1] + b3v.y + sw * (b1v.y - s2[1]);
            cv.z = s3[2] + b3v.z + sw * (b1v.z - s2[2]);
            cv.w = s3[3] + b3v.w + sw * (b1v.w - s2[3]);
            ((float4*)(g_c + (size_t)row * 64))[q] = cv;
        }
    }
}

// ---------------- edge aggregation (CSR, 64 threads/node, unroll 8) ----------------
__global__ void __launch_bounds__(256) k_edge() {
    int v = blockIdx.x * 4 + (threadIdx.x >> 6);
    int k = threadIdx.x & 63;
    if (v >= N_NODES) return;
    int lo = g_rowptr[v], hi = g_rowptr[v + 1];
    const float* __restrict__ A = g_a;
    float acc = g_c[v * HID + k];
    int e = lo;
    for (; e + 7 < hi; e += 8) {
        int   s[8];
        float w[8];
#pragma unroll
        for (int j = 0; j < 8; j++) { s[j] = g_src[e + j]; w[j] = g_ew[e + j]; }
        float av[8];
#pragma unroll
        for (int j = 0; j < 8; j++) av[j] = A[s[j] * HID + k];
#pragma unroll
        for (int j = 0; j < 8; j++) acc += w[j] * av[j];
    }
    for (; e < hi; e++) acc += g_ew[e] * A[g_src[e] * HID + k];
    g_h[v * HID + k] = fmaxf(acc, 0.f);
}

// ---------------- pool + MLP head ----------------
__device__ __forceinline__ int lb_idx(const void* b, int val) {
    int lo = 0, hi = N_NODES;
    if (g_idx64) {
        const long long* p = (const long long*)b;
        long long v = (long long)val;
        while (lo < hi) { int m = (lo + hi) >> 1; if (p[m] < v) lo = m + 1; else hi = m; }
    } else {
        const int* p = (const int*)b;
        while (lo < hi) { int m = (lo + hi) >> 1; if (p[m] < val) lo = m + 1; else hi = m; }
    }
    return lo;
}

__global__ void __launch_bounds__(64) k_pool(
    const void* __restrict__ batch,
    const float* __restrict__ l1w, const float* __restrict__ l1b,
    const float* __restrict__ l2w, const float* __restrict__ l2b,
    float* __restrict__ out)
{
    int g = blockIdx.x;
    int k = threadIdx.x;
    __shared__ int s_lo, s_hi;
    __shared__ float gx[HID], hh[HID];
    if (k == 0) s_lo = lb_idx(batch, g);
    if (k == 1) s_hi = lb_idx(batch, g + 1);
    __syncthreads();
    int lo = s_lo, hi = s_hi;
    float s = 0.f;
    for (int v = lo; v < hi; v++) s += g_h[v * HID + k];
    float cnt = (float)(hi - lo);
    gx[k] = s / fmaxf(cnt, 1.f);
    __syncthreads();
    float acc = l1b[k];
#pragma unroll 8
    for (int i = 0; i < HID; i++) acc += gx[i] * l1w[i * HID + k];
    hh[k] = fmaxf(acc, 0.f);
    __syncthreads();
    if (k < 3) {
        float o = l2b[k];
#pragma unroll 8
        for (int i = 0; i < HID; i++) o += hh[i] * l2w[i * 3 + k];
        out[g * 3 + k] = o;
    }
}

// ---------------- launch ----------------
extern "C" void kernel_launch(void* const* d_in, const int* in_sizes, int n_in,
                              void* d_out, int out_size) {
    const float* x       = (const float*)d_in[0];
    const void*  eindex  = d_in[1];
    const float* eattr   = (const float*)d_in[2];
    const void*  batch   = d_in[3];
    const float* emb_w   = (const float*)d_in[4];
    const float* emb_b   = (const float*)d_in[5];
    const float* conv_w1 = (const float*)d_in[6];
    const float* conv_b1 = (const float*)d_in[7];
    const float* conv_w2 = (const float*)d_in[8];
    const float* conv_w3 = (const float*)d_in[9];
    const float* conv_b3 = (const float*)d_in[10];
    const float* lin1_w  = (const float*)d_in[11];
    const float* lin1_b  = (const float*)d_in[12];
    const float* lin2_w  = (const float*)d_in[13];
    const float* lin2_b  = (const float*)d_in[14];
    float*       out     = (float*)d_out;

    k_init<<<(N_NODES * HID + 255) / 256, 256>>>(eindex, x, emb_w, emb_b);
    k_hist<<<(N_EDGES + 255) / 256, 256>>>(eindex, eattr);
    k_scan1<<<SCAN_NBLK, 1024>>>();
    k_scan3<<<SCAN_NBLK, 1024>>>();
    k_fill<<<(N_EDGES + 255) / 256, 256>>>(eindex, eattr);

    for (int l = 0; l < NL; l++) {
        const float* W1 = conv_w1 + l * HID * HID;
        const float* B1 = conv_b1 + l * HID;
        const float* W2 = conv_w2 + l * HID * HID;
        const float* W3 = conv_w3 + l * HID * HID;
        const float* B3 = conv_b3 + l * HID;
        k_gemm_mma<<<(N_NODES + 63) / 64, 128>>>(W1, B1, W2, W3, B3);
        k_edge<<<(N_NODES + 3) / 4, 256>>>();
    }

    k_pool<<<N_GRAPHS, 64>>>(batch, lin1_w, lin1_b, lin2_w, lin2_b, out);
}

// round 8
// speedup vs baseline: 1.8352x; 1.3668x over previous
#include <cuda_runtime.h>
#include <cuda_bf16.h>
#include <cuda_fp16.h>
#include <mma.h>
#include <cstdint>

using namespace nvcuda;

#define N_NODES 100000
#define N_EDGES 3200000
#define N_GRAPHS 1000
#define HID 64
#define NL 4

#define SCAN_NBLK ((N_NODES + 1023) / 1024)   // 98
#define AST 72                                 // bf16 smem stride (elems)
#define DST 72                                 // fp32 strip stride (elems)

// ---------------- device scratch ----------------
__device__ float  g_h[N_NODES * HID];
__device__ __half g_af[N_NODES * HID];   // a = h@W1 (raw, no bias) in fp16 for cheap gather
__device__ float  g_c[N_NODES * HID];    // c = D3 + b3 + sumw*b1 - sumw*D2
__device__ int    g_deg[N_NODES];
__device__ float  g_sumw[N_NODES];
__device__ int    g_rowptr[N_NODES + 1];
__device__ int    g_cursor[N_NODES];
__device__ int    g_src[N_EDGES];
__device__ float  g_ew[N_EDGES];
__device__ int    g_idx64;
__device__ int    g_psum[SCAN_NBLK];

__device__ __forceinline__ int idx_at(const void* p, long long pos) {
    return g_idx64 ? (int)((const long long*)p)[pos] : ((const int*)p)[pos];
}
__device__ __forceinline__ int clampi(int v, int hi) {
    return v < 0 ? 0 : (v >= hi ? hi - 1 : v);
}

// ---------------- fused init: dtype probe + zero + embed ----------------
__global__ void k_init(const void* __restrict__ ei,
                       const float* __restrict__ x,
                       const float* __restrict__ w,
                       const float* __restrict__ b) {
    int i = blockIdx.x * blockDim.x + threadIdx.x;
    if (i == 0) {
        const long long* p = (const long long*)ei;
        int ok64 = 1;
        for (int j = 0; j < 64; j++) {
            long long v = p[j];
            if (v < 0 || v >= N_NODES) { ok64 = 0; break; }
        }
        g_idx64 = ok64;
    }
    if (i < N_NODES) { g_deg[i] = 0; g_sumw[i] = 0.f; }
    if (i < N_NODES * HID) {
        int v = i >> 6, k = i & 63;
        const float* xr = x + v * 4;
        float acc = b[k];
#pragma unroll
        for (int j = 0; j < 4; j++) acc += xr[j] * w[j * HID + k];
        g_h[i] = acc;
    }
}

// ---------------- CSR build ----------------
__global__ void k_hist(const void* __restrict__ ei) {
    int e = blockIdx.x * blockDim.x + threadIdx.x;
    if (e < N_EDGES) {
        int dst = clampi(idx_at(ei, (long long)N_EDGES + e), N_NODES);
        atomicAdd(&g_deg[dst], 1);
    }
}

__global__ void __launch_bounds__(1024) k_scan1() {
    __shared__ int sh[32];
    int i = blockIdx.x * 1024 + threadIdx.x;
    int v = (i < N_NODES) ? g_deg[i] : 0;
    for (int o = 16; o > 0; o >>= 1) v += __shfl_down_sync(0xffffffffu, v, o);
    if ((threadIdx.x & 31) == 0) sh[threadIdx.x >> 5] = v;
    __syncthreads();
    if (threadIdx.x < 32) {
        int s = sh[threadIdx.x];
        for (int o = 16; o > 0; o >>= 1) s += __shfl_down_sync(0xffffffffu, s, o);
        if (threadIdx.x == 0) g_psum[blockIdx.x] = s;
    }
}

__global__ void __launch_bounds__(1024) k_scan3() {
    __shared__ int sh[1024];
    __shared__ int swr[32];
    __shared__ int soff;
    int t = threadIdx.x;
    int po = (t < blockIdx.x) ? g_psum[t] : 0;
    for (int o = 16; o > 0; o >>= 1) po += __shfl_down_sync(0xffffffffu, po, o);
    if ((t & 31) == 0) swr[t >> 5] = po;
    __syncthreads();
    if (t < 32) {
        int s = swr[t];
        for (int o = 16; o > 0; o >>= 1) s += __shfl_down_sync(0xffffffffu, s, o);
        if (t == 0) soff = s;
    }
    int i = blockIdx.x * 1024 + t;
    int d = (i < N_NODES) ? g_deg[i] : 0;
    sh[t] = d;
    __syncthreads();
    for (int off = 1; off < 1024; off <<= 1) {
        int v = (t >= off) ? sh[t - off] : 0;
        __syncthreads();
        sh[t] += v;
        __syncthreads();
    }
    if (i < N_NODES) {
        int excl = soff + sh[t] - d;
        g_rowptr[i] = excl;
        g_cursor[i] = excl;
    }
    if (i == 0) g_rowptr[N_NODES] = N_EDGES;
}

// fill also accumulates sumw (saves a separate float-atomic pass in k_hist)
__global__ void k_fill(const void* __restrict__ ei, const float* __restrict__ ea) {
    int e = blockIdx.x * blockDim.x + threadIdx.x;
    if (e < N_EDGES) {
        int src = clampi(idx_at(ei, e), N_NODES);
        int dst = clampi(idx_at(ei, (long long)N_EDGES + e), N_NODES);
        float w = ea[e];
        atomicAdd(&g_sumw[dst], w);
        int pos = atomicAdd(&g_cursor[dst], 1);
        if (pos < N_EDGES) {
            g_src[pos] = src;
            g_ew[pos]  = w;
        }
    }
}

// ---------------- WMMA bf16 split-precision fused 3-matrix GEMM ----------------
// D1 = h@W1 -> g_af (fp16, raw). D2 = h@W2, D3 = h@W3.
// g_c = D3 + b3 + sumw*b1 - sumw*D2   (b1 folded via sum_e ew*b1 = sumw*b1)
// Split: X = X_hi + X_lo (bf16 each); D ≈ hi*hi + lo*hi + hi*lo, fp32 accum.
// 64 rows/CTA, 4 warps, warp w owns rows w*16..w*16+15.
__global__ void __launch_bounds__(128) k_gemm_mma(
    const float* __restrict__ W1, const float* __restrict__ B1,
    const float* __restrict__ W2, const float* __restrict__ W3,
    const float* __restrict__ B3)
{
    __shared__ __align__(16) char sm[36864];
    __nv_bfloat16* sAhi = (__nv_bfloat16*)(sm);
    __nv_bfloat16* sAlo = (__nv_bfloat16*)(sm + 9216);
    __nv_bfloat16* sWhi = (__nv_bfloat16*)(sm + 18432);
    __nv_bfloat16* sWlo = (__nv_bfloat16*)(sm + 27648);
    float* stripA = (float*)sm;             // 4 warps x 16x72 fp32 (reuses A region)
    float* stripW = (float*)(sm + 18432);   // 4 warps x 16x72 fp32 (reuses W region)

    const int t = threadIdx.x;
    const int w = t >> 5;
    const int lid = t & 31;
    const int row0 = blockIdx.x * 64;

    // ---- A tile: load h, split hi/lo bf16 ----
    for (int i = t; i < 2048; i += 128) {        // 64 rows x 32 float2
        int r = i >> 5, kp = i & 31;
        int grow = row0 + r;
        float2 hv = make_float2(0.f, 0.f);
        if (grow < N_NODES) hv = ((const float2*)g_h)[grow * 32 + kp];
        __nv_bfloat16 h0 = __float2bfloat16(hv.x);
        __nv_bfloat16 h1 = __float2bfloat16(hv.y);
        sAhi[r * AST + kp * 2]     = h0;
        sAhi[r * AST + kp * 2 + 1] = h1;
        sAlo[r * AST + kp * 2]     = __float2bfloat16(hv.x - __bfloat162float(h0));
        sAlo[r * AST + kp * 2 + 1] = __float2bfloat16(hv.y - __bfloat162float(h1));
    }
    __syncthreads();

    wmma::fragment<wmma::matrix_a, 16, 16, 16, __nv_bfloat16, wmma::row_major> ahi[4], alo[4];
#pragma unroll
    for (int k = 0; k < 4; k++) {
        wmma::load_matrix_sync(ahi[k], sAhi + (w * 16) * AST + k * 16, AST);
        wmma::load_matrix_sync(alo[k], sAlo + (w * 16) * AST + k * 16, AST);
    }

    const float* Ws[3] = { W1, W2, W3 };
    wmma::fragment<wmma::accumulator, 16, 16, 16, float> d3f[4];

#pragma unroll
    for (int mat = 0; mat < 3; mat++) {
        __syncthreads();   // all warps done with previous W reads / strip reads
        const float* W = Ws[mat];
        for (int i = t; i < 2048; i += 128) {    // 64 k-rows x 32 float2
            int r = i >> 5, np = i & 31;
            float2 wv = ((const float2*)W)[r * 32 + np];
            __nv_bfloat16 h0 = __float2bfloat16(wv.x);
            __nv_bfloat16 h1 = __float2bfloat16(wv.y);
            sWhi[r * AST + np * 2]     = h0;
            sWhi[r * AST + np * 2 + 1] = h1;
            sWlo[r * AST + np * 2]     = __float2bfloat16(wv.x - __bfloat162float(h0));
            sWlo[r * AST + np * 2 + 1] = __float2bfloat16(wv.y - __bfloat162float(h1));
        }
        __syncthreads();

#pragma unroll
        for (int n = 0; n < 4; n++) {
            wmma::fragment<wmma::accumulator, 16, 16, 16, float> d;
            wmma::fill_fragment(d, 0.f);
#pragma unroll
            for (int k = 0; k < 4; k++) {
                wmma::fragment<wmma::matrix_b, 16, 16, 16, __nv_bfloat16, wmma::row_major> bh, bl;
                wmma::load_matrix_sync(bh, sWhi + (k * 16) * AST + n * 16, AST);
                wmma::mma_sync(d, ahi[k], bh, d);
                wmma::mma_sync(d, alo[k], bh, d);
                wmma::load_matrix_sync(bl, sWlo + (k * 16) * AST + n * 16, AST);
                wmma::mma_sync(d, ahi[k], bl, d);
            }
            if (mat == 2) {
                d3f[n] = d;
            } else {
                // D1 and D2 go to the warp-private strip (A region; a-frags in regs)
                wmma::store_matrix_sync(stripA + w * 16 * DST + n * 16, d, DST,
                                        wmma::mem_row_major);
            }
        }

        if (mat == 0) {
            // flush D1 strip -> g_af as fp16
            __syncwarp();
            for (int i = lid; i < 512; i += 32) {   // 16 rows x 32 half2
                int r = i >> 5, q = i & 31;
                int row = row0 + w * 16 + r;
                if (row < N_NODES) {
                    const float* s = stripA + (w * 16 + r) * DST + q * 2;
                    ((__half2*)(g_af + (size_t)row * 64))[q] = __floats2half2_rn(s[0], s[1]);
                }
            }
            __syncwarp();
        }
    }

    // ---- D3 to strips (W region) after everyone is done reading weights ----
    __syncthreads();
#pragma unroll
    for (int n = 0; n < 4; n++)
        wmma::store_matrix_sync(stripW + w * 16 * DST + n * 16, d3f[n], DST,
                                wmma::mem_row_major);
    __syncwarp();

    // ---- combine: g_c = D3 + b3 + sumw*b1 - sumw*D2 ----
    for (int i = lid; i < 256; i += 32) {           // 16 rows x 16 float4
        int r = i >> 4, q = i & 15;
        int row = row0 + w * 16 + r;
        if (row < N_NODES) {
            float sw = g_sumw[row];
            const float* s2 = stripA + (w * 16 + r) * DST + q * 4;
            const float* s3 = stripW + (w * 16 + r) * DST + q * 4;
            float4 b1v = ((const float4*)B1)[q];
            float4 b3v = ((const float4*)B3)[q];
            float4 cv;
            cv.x = s3[0] + b3v.x + sw * (b1v.x - s2[0]);
            cv.y = s3[1] + b3v.y + sw * (b1v.y - s2[1]);
            cv.z = s3[2] + b3v.z + sw * (b1v.z - s2[2]);
            cv.w = s3[3] + b3v.w + sw * (b1v.w - s2[3]);
            ((float4*)(g_c + (size_t)row * 64))[q] = cv;
        }
    }
}

// ---------------- edge aggregation (CSR, fp16 gather, 32 threads/node) ----------------
// h = relu(sum_e ew * a_fp16[src] + c); one warp per node, half2 per lane.
__global__ void __launch_bounds__(256) k_edge() {
    int v = blockIdx.x * 8 + (threadIdx.x >> 5);
    int kp = threadIdx.x & 31;
    if (v >= N_NODES) return;
    int lo = g_rowptr[v], hi = g_rowptr[v + 1];
    const __half2* __restrict__ A = (const __half2*)g_af;
    float2 acc = ((const float2*)g_c)[v * 32 + kp];
    int e = lo;
    for (; e + 7 < hi; e += 8) {
        int   s[8];
        float w[8];
#pragma unroll
        for (int j = 0; j < 8; j++) { s[j] = g_src[e + j]; w[j] = g_ew[e + j]; }
#pragma unroll
        for (int j = 0; j < 8; j++) {
            float2 av = __half22float2(A[s[j] * 32 + kp]);
            acc.x += w[j] * av.x;
            acc.y += w[j] * av.y;
        }
    }
    for (; e < hi; e++) {
        float2 av = __half22float2(A[g_src[e] * 32 + kp]);
        float  w  = g_ew[e];
        acc.x += w * av.x;
        acc.y += w * av.y;
    }
    acc.x = fmaxf(acc.x, 0.f);
    acc.y = fmaxf(acc.y, 0.f);
    ((float2*)g_h)[v * 32 + kp] = acc;
}

// ---------------- pool + MLP head ----------------
__device__ __forceinline__ int lb_idx(const void* b, int val) {
    int lo = 0, hi = N_NODES;
    if (g_idx64) {
        const long long* p = (const long long*)b;
        long long v = (long long)val;
        while (lo < hi) { int m = (lo + hi) >> 1; if (p[m] < v) lo = m + 1; else hi = m; }
    } else {
        const int* p = (const int*)b;
        while (lo < hi) { int m = (lo + hi) >> 1; if (p[m] < val) lo = m + 1; else hi = m; }
    }
    return lo;
}

__global__ void __launch_bounds__(64) k_pool(
    const void* __restrict__ batch,
    const float* __restrict__ l1w, const float* __restrict__ l1b,
    const float* __restrict__ l2w, const float* __restrict__ l2b,
    float* __restrict__ out)
{
    int g = blockIdx.x;
    int k = threadIdx.x;
    __shared__ int s_lo, s_hi;
    __shared__ float gx[HID], hh[HID];
    if (k == 0) s_lo = lb_idx(batch, g);
    if (k == 1) s_hi = lb_idx(batch, g + 1);
    __syncthreads();
    int lo = s_lo, hi = s_hi;
    float s = 0.f;
    for (int v = lo; v < hi; v++) s += g_h[v * HID + k];
    float cnt = (float)(hi - lo);
    gx[k] = s / fmaxf(cnt, 1.f);
    __syncthreads();
    float acc = l1b[k];
#pragma unroll 8
    for (int i = 0; i < HID; i++) acc += gx[i] * l1w[i * HID + k];
    hh[k] = fmaxf(acc, 0.f);
    __syncthreads();
    if (k < 3) {
        float o = l2b[k];
#pragma unroll 8
        for (int i = 0; i < HID; i++) o += hh[i] * l2w[i * 3 + k];
        out[g * 3 + k] = o;
    }
}

// ---------------- launch ----------------
extern "C" void kernel_launch(void* const* d_in, const int* in_sizes, int n_in,
                              void* d_out, int out_size) {
    const float* x       = (const float*)d_in[0];
    const void*  eindex  = d_in[1];
    const float* eattr   = (const float*)d_in[2];
    const void*  batch   = d_in[3];
    const float* emb_w   = (const float*)d_in[4];
    const float* emb_b   = (const float*)d_in[5];
    const float* conv_w1 = (const float*)d_in[6];
    const float* conv_b1 = (const float*)d_in[7];
    const float* conv_w2 = (const float*)d_in[8];
    const float* conv_w3 = (const float*)d_in[9];
    const float* conv_b3 = (const float*)d_in[10];
    const float* lin1_w  = (const float*)d_in[11];
    const float* lin1_b  = (const float*)d_in[12];
    const float* lin2_w  = (const float*)d_in[13];
    const float* lin2_b  = (const float*)d_in[14];
    float*       out     = (float*)d_out;

    k_init<<<(N_NODES * HID + 255) / 256, 256>>>(eindex, x, emb_w, emb_b);
    k_hist<<<(N_EDGES + 255) / 256, 256>>>(eindex);
    k_scan1<<<SCAN_NBLK, 1024>>>();
    k_scan3<<<SCAN_NBLK, 1024>>>();
    k_fill<<<(N_EDGES + 255) / 256, 256>>>(eindex, eattr);

    for (int l = 0; l < NL; l++) {
        const float* W1 = conv_w1 + l * HID * HID;
        const float* B1 = conv_b1 + l * HID;
        const float* W2 = conv_w2 + l * HID * HID;
        const float* W3 = conv_w3 + l * HID * HID;
        const float* B3 = conv_b3 + l * HID;
        k_gemm_mma<<<(N_NODES + 63) / 64, 128>>>(W1, B1, W2, W3, B3);
        k_edge<<<(N_NODES + 7) / 8, 256>>>();
    }

    k_pool<<<N_GRAPHS, 64>>>(batch, lin1_w, lin1_b, lin2_w, lin2_b, out);
}